// round 12
// baseline (speedup 1.0000x reference)
#include <cuda_runtime.h>
#include <cuda_fp16.h>
#include <cstdint>

#define H_IN   224
#define W_IN   224
#define NPIX   49284
#define KD     576
#define KC     64
#define NCHUNK 9
#define BN     64          // N pixels per CTA (N-split)

#define A_STRIDE 72        // fp16 per A row (64 k + 8 pad)
#define B_STRIDE 72        // fp16 per B row (64 n + 8 pad)

#define A_TILE_B (128 * A_STRIDE * 2)   // 18432 B
#define B_TILE_B (KC * B_STRIDE * 2)    // 9216 B
#define STAGE_B  (A_TILE_B + B_TILE_B)  // 27648 B
#define OFF_A(st) ((st) * STAGE_B)
#define OFF_B(st) ((st) * STAGE_B + A_TILE_B)
#define NSTAGE 2
#define SMEM_TOTAL (NSTAGE * STAGE_B)   // 55296 B -> 2 CTAs/SM

#define PLANE   (64 * 224 * 222)
#define CSTRIDE (224 * 222)

// ---- persistent scratch ----
__device__ __half g_Wh[128 * KD];
__device__ __half g_Xs[3 * PLANE + 1024];

__device__ __forceinline__ uint32_t smem_u32(const void* p) {
    uint32_t a;
    asm("{ .reg .u64 t; cvta.to.shared.u64 t, %1; cvt.u32.u64 %0, t; }" : "=r"(a) : "l"(p));
    return a;
}
__device__ __forceinline__ void ldsm_x4(uint32_t (&r)[4], uint32_t addr) {
    asm volatile("ldmatrix.sync.aligned.m8n8.x4.shared.b16 {%0,%1,%2,%3}, [%4];"
                 : "=r"(r[0]), "=r"(r[1]), "=r"(r[2]), "=r"(r[3]) : "r"(addr));
}
__device__ __forceinline__ void ldsm_x4t(uint32_t (&r)[4], uint32_t addr) {
    asm volatile("ldmatrix.sync.aligned.m8n8.x4.trans.shared.b16 {%0,%1,%2,%3}, [%4];"
                 : "=r"(r[0]), "=r"(r[1]), "=r"(r[2]), "=r"(r[3]) : "r"(addr));
}
__device__ __forceinline__ void mma_f16(float (&d)[4], const uint32_t (&a)[4],
                                        uint32_t b0, uint32_t b1) {
    asm volatile(
        "mma.sync.aligned.m16n8k16.row.col.f32.f16.f16.f32 "
        "{%0,%1,%2,%3}, {%4,%5,%6,%7}, {%8,%9}, {%0,%1,%2,%3};"
        : "+f"(d[0]), "+f"(d[1]), "+f"(d[2]), "+f"(d[3])
        : "r"(a[0]), "r"(a[1]), "r"(a[2]), "r"(a[3]), "r"(b0), "r"(b1));
}
__device__ __forceinline__ void cp16(uint32_t dst, const void* src) {
    asm volatile("cp.async.cg.shared.global [%0], [%1], 16;" :: "r"(dst), "l"(src));
}
__device__ __forceinline__ void cp4(uint32_t dst, const void* src) {
    asm volatile("cp.async.ca.shared.global [%0], [%1], 4;" :: "r"(dst), "l"(src));
}
#define CP_COMMIT() asm volatile("cp.async.commit_group;" ::: "memory")
#define CP_WAIT0()  asm volatile("cp.async.wait_group 0;" ::: "memory")

// ---- fused pre-kernel: weights fp16 + 3 shifted x planes ----
#define WBLKS 72
#define XBLKS 6216
__global__ void split_pre_kernel(const float* __restrict__ w, const float* __restrict__ x) {
    const int b = blockIdx.x;
    if (b < WBLKS) {
        const int i = b * 256 + threadIdx.x;
        const float4 v = reinterpret_cast<const float4*>(w)[i];
        *reinterpret_cast<ushort4*>(&g_Wh[4 * i]) =
            make_ushort4(__half_as_ushort(__float2half_rn(v.x)),
                         __half_as_ushort(__float2half_rn(v.y)),
                         __half_as_ushort(__float2half_rn(v.z)),
                         __half_as_ushort(__float2half_rn(v.w)));
    } else {
        const int gid = (b - WBLKS) * 256 + threadIdx.x;
        const int c   = gid / (224 * 111);
        const int rem = gid - c * (224 * 111);
        const int h   = rem / 111;
        const int p   = rem - h * 111;
        const int wcol = 2 * p;
        const float* xr = x + ((size_t)c * 224 + h) * 224 + wcol;
        const float2 u0 = *reinterpret_cast<const float2*>(xr);
        const float2 u1 = *reinterpret_cast<const float2*>(xr + 2);
        const uint32_t c0 = __half_as_ushort(__float2half_rn(u0.x));
        const uint32_t c1 = __half_as_ushort(__float2half_rn(u0.y));
        const uint32_t c2 = __half_as_ushort(__float2half_rn(u1.x));
        const uint32_t c3 = __half_as_ushort(__float2half_rn(u1.y));
        const size_t base = ((size_t)c * 224 + h) * 222 + wcol;
        *reinterpret_cast<uint32_t*>(&g_Xs[0 * PLANE + base]) = c0 | (c1 << 16);
        *reinterpret_cast<uint32_t*>(&g_Xs[1 * PLANE + base]) = c1 | (c2 << 16);
        *reinterpret_cast<uint32_t*>(&g_Xs[2 * PLANE + base]) = c2 | (c3 << 16);
    }
}

// ---- main kernel: 128x64 tile, 256 threads, 2 CTAs/SM ----
__global__ __launch_bounds__(256, 2)
void conv_mma_kernel(float* __restrict__ out)
{
    extern __shared__ __align__(16) char smem[];
    const int tid  = threadIdx.x;
    const int lane = tid & 31;
    const int wid  = tid >> 5;          // 0..7
    const int wm   = wid >> 1;          // 0..3 -> 32-row band
    const int wn   = wid & 1;           // 0..1 -> 32-col band
    const int n_base = blockIdx.x * BN;

    float acc[2][4][4];
#pragma unroll
    for (int i = 0; i < 2; i++)
#pragma unroll
        for (int j = 0; j < 4; j++)
#pragma unroll
            for (int k = 0; k < 4; k++) acc[i][j][k] = 0.0f;

    // A: 2 threads per row (128 rows), each 32 halves via 4x cp16
    const int a_co = tid >> 1;            // 0..127
    const int a_kq = (tid & 1) * 32;      // 0 or 32
    // B: 4 threads per row (64 rows), each 16 halves via 8x cp4
    const int b_k   = tid >> 2;           // 0..63
    const int b_seg = (tid & 3) * 16;     // halves

    auto issue = [&](int chunk, int st) {
        const int k0 = chunk * KC;
        const uint32_t arow = smem_u32(smem + OFF_A(st) + (a_co * A_STRIDE + a_kq) * 2);
        const __half* asrc = &g_Wh[a_co * KD + k0 + a_kq];
#pragma unroll
        for (int j = 0; j < 4; j++)
            cp16(arow + j * 16, asrc + j * 8);
        const int k  = k0 + b_k;
        const int c  = k / 9;
        const int rs = k - c * 9;
        const int r  = rs / 3;
        const int s  = rs - r * 3;
        const __half* src = g_Xs + (size_t)s * PLANE + c * CSTRIDE + r * 222 + n_base + b_seg;
        const uint32_t dst = smem_u32(smem + OFF_B(st) + (b_k * B_STRIDE + b_seg) * 2);
#pragma unroll
        for (int j = 0; j < 8; j++)
            cp4(dst + j * 4, src + j * 2);
    };

    // prologue
    issue(0, 0);
    CP_COMMIT();
    CP_WAIT0();
    __syncthreads();

    const int bt_row = (lane & 7) + ((lane >> 3) & 1) * 8;
    const int bt_col = ((lane >> 4) & 1) * 8;

    for (int i = 0; i < NCHUNK; i++) {
        const int st = i & 1, nxt = (i + 1) & 1;
        if (i + 1 < NCHUNK) { issue(i + 1, nxt); CP_COMMIT(); }

        const char* pA = smem + OFF_A(st);
        const char* pB = smem + OFF_B(st);

#pragma unroll
        for (int ks = 0; ks < 4; ks++) {
            const int kb = ks * 16;
            uint32_t ah[2][4];
#pragma unroll
            for (int mt = 0; mt < 2; mt++) {
                const int row = wm * 32 + mt * 16 + (lane & 15);
                const int col = kb + ((lane >> 4) << 3);
                ldsm_x4(ah[mt], smem_u32(pA + (row * A_STRIDE + col) * 2));
            }
            uint32_t bf[2][4];
            const int krow = kb + bt_row;
#pragma unroll
            for (int pr = 0; pr < 2; pr++) {
                const int ncol = wn * 32 + pr * 16 + bt_col;
                ldsm_x4t(bf[pr], smem_u32(pB + (krow * B_STRIDE + ncol) * 2));
            }
#pragma unroll
            for (int mt = 0; mt < 2; mt++)
#pragma unroll
                for (int nt = 0; nt < 4; nt++) {
                    const int pr = nt >> 1, hf = (nt & 1) * 2;
                    mma_f16(acc[mt][nt], ah[mt], bf[pr][hf], bf[pr][hf + 1]);
                }
        }

        if (i + 1 < NCHUNK) CP_WAIT0();
        __syncthreads();
    }

    // epilogue
#pragma unroll
    for (int mt = 0; mt < 2; mt++) {
        const int row0 = wm * 32 + mt * 16 + (lane >> 2);
#pragma unroll
        for (int nt = 0; nt < 4; nt++) {
            const int n = n_base + wn * 32 + nt * 8 + 2 * (lane & 3);
            if (n < NPIX) {
                *reinterpret_cast<float2*>(out + (size_t)row0 * NPIX + n) =
                    make_float2(acc[mt][nt][0], acc[mt][nt][1]);
                *reinterpret_cast<float2*>(out + (size_t)(row0 + 8) * NPIX + n) =
                    make_float2(acc[mt][nt][2], acc[mt][nt][3]);
            }
        }
    }
}

extern "C" void kernel_launch(void* const* d_in, const int* in_sizes, int n_in,
                              void* d_out, int out_size)
{
    const float* x = (const float*)d_in[0];   // (64, 224, 224) f32
    const float* w = (const float*)d_in[1];   // (128, 64, 3, 3) f32
    float* out = (float*)d_out;               // (128, 222, 222) f32

    split_pre_kernel<<<WBLKS + XBLKS, 256>>>(w, x);

    cudaFuncSetAttribute(conv_mma_kernel, cudaFuncAttributeMaxDynamicSharedMemorySize, SMEM_TOTAL);
    const int grid = (NPIX + BN - 1) / BN;    // 771
    conv_mma_kernel<<<grid, 256, SMEM_TOTAL>>>(out);
}

// round 14
// speedup vs baseline: 1.2887x; 1.2887x over previous
#include <cuda_runtime.h>
#include <cuda_fp16.h>
#include <cstdint>

#define H_IN   224
#define W_IN   224
#define NPIX   49284
#define KD     576
#define KC     64
#define NCHUNK 9
#define BN     128

#define A_STRIDE 72     // fp16 per A row (64 k + 8 pad)
#define B_STRIDE 136    // fp16 per B row (128 n + 8 pad)

#define A_TILE_B (128 * A_STRIDE * 2)   // 18432 B
#define B_TILE_B (KC * B_STRIDE * 2)    // 17408 B
#define STAGE_B  (A_TILE_B + B_TILE_B)  // 35840 B
#define OFF_A(st) ((st) * STAGE_B)
#define OFF_B(st) ((st) * STAGE_B + A_TILE_B)
#define NSTAGE 2
#define SMEM_TOTAL (NSTAGE * STAGE_B)   // 55296 B -> 2 CTAs/SM of 512 thr

#define PLANE   (64 * 224 * 222)
#define CSTRIDE (224 * 222)

// ---- persistent scratch ----
__device__ __half g_Wh[128 * KD];
__device__ __half g_Xs[3 * PLANE + 1024];

__device__ __forceinline__ uint32_t smem_u32(const void* p) {
    uint32_t a;
    asm("{ .reg .u64 t; cvta.to.shared.u64 t, %1; cvt.u32.u64 %0, t; }" : "=r"(a) : "l"(p));
    return a;
}
__device__ __forceinline__ void ldsm_x4(uint32_t (&r)[4], uint32_t addr) {
    asm volatile("ldmatrix.sync.aligned.m8n8.x4.shared.b16 {%0,%1,%2,%3}, [%4];"
                 : "=r"(r[0]), "=r"(r[1]), "=r"(r[2]), "=r"(r[3]) : "r"(addr));
}
__device__ __forceinline__ void ldsm_x4t(uint32_t (&r)[4], uint32_t addr) {
    asm volatile("ldmatrix.sync.aligned.m8n8.x4.trans.shared.b16 {%0,%1,%2,%3}, [%4];"
                 : "=r"(r[0]), "=r"(r[1]), "=r"(r[2]), "=r"(r[3]) : "r"(addr));
}
__device__ __forceinline__ void mma_f16(float (&d)[4], const uint32_t (&a)[4],
                                        uint32_t b0, uint32_t b1) {
    asm volatile(
        "mma.sync.aligned.m16n8k16.row.col.f32.f16.f16.f32 "
        "{%0,%1,%2,%3}, {%4,%5,%6,%7}, {%8,%9}, {%0,%1,%2,%3};"
        : "+f"(d[0]), "+f"(d[1]), "+f"(d[2]), "+f"(d[3])
        : "r"(a[0]), "r"(a[1]), "r"(a[2]), "r"(a[3]), "r"(b0), "r"(b1));
}
__device__ __forceinline__ void cp16(uint32_t dst, const void* src) {
    asm volatile("cp.async.cg.shared.global [%0], [%1], 16;" :: "r"(dst), "l"(src));
}
__device__ __forceinline__ void cp4(uint32_t dst, const void* src) {
    asm volatile("cp.async.ca.shared.global [%0], [%1], 4;" :: "r"(dst), "l"(src));
}
#define CP_COMMIT() asm volatile("cp.async.commit_group;" ::: "memory")
#define CP_WAIT0()  asm volatile("cp.async.wait_group 0;" ::: "memory")

// ---- fused pre-kernel: weights fp16 + 3 shifted x planes ----
#define WBLKS 72
#define XBLKS 6216
__global__ void split_pre_kernel(const float* __restrict__ w, const float* __restrict__ x) {
    const int b = blockIdx.x;
    if (b < WBLKS) {
        const int i = b * 256 + threadIdx.x;
        const float4 v = reinterpret_cast<const float4*>(w)[i];
        *reinterpret_cast<ushort4*>(&g_Wh[4 * i]) =
            make_ushort4(__half_as_ushort(__float2half_rn(v.x)),
                         __half_as_ushort(__float2half_rn(v.y)),
                         __half_as_ushort(__float2half_rn(v.z)),
                         __half_as_ushort(__float2half_rn(v.w)));
    } else {
        const int gid = (b - WBLKS) * 256 + threadIdx.x;
        const int c   = gid / (224 * 111);
        const int rem = gid - c * (224 * 111);
        const int h   = rem / 111;
        const int p   = rem - h * 111;
        const int wcol = 2 * p;
        const float* xr = x + ((size_t)c * 224 + h) * 224 + wcol;
        const float2 u0 = *reinterpret_cast<const float2*>(xr);
        const float2 u1 = *reinterpret_cast<const float2*>(xr + 2);
        const uint32_t c0 = __half_as_ushort(__float2half_rn(u0.x));
        const uint32_t c1 = __half_as_ushort(__float2half_rn(u0.y));
        const uint32_t c2 = __half_as_ushort(__float2half_rn(u1.x));
        const uint32_t c3 = __half_as_ushort(__float2half_rn(u1.y));
        const size_t base = ((size_t)c * 224 + h) * 222 + wcol;
        *reinterpret_cast<uint32_t*>(&g_Xs[0 * PLANE + base]) = c0 | (c1 << 16);
        *reinterpret_cast<uint32_t*>(&g_Xs[1 * PLANE + base]) = c1 | (c2 << 16);
        *reinterpret_cast<uint32_t*>(&g_Xs[2 * PLANE + base]) = c2 | (c3 << 16);
    }
}

// ---- main implicit-GEMM kernel: 1-term fp16, 2 CTAs/SM target ----
__global__ __launch_bounds__(512, 2)
void conv_mma_kernel(float* __restrict__ out)
{
    extern __shared__ __align__(16) char smem[];
    const int tid  = threadIdx.x;
    const int lane = tid & 31;
    const int wid  = tid >> 5;
    const int wm   = wid >> 2;
    const int wn   = wid & 3;
    const int n_base = blockIdx.x * BN;

    float acc[2][4][4];
#pragma unroll
    for (int i = 0; i < 2; i++)
#pragma unroll
        for (int j = 0; j < 4; j++)
#pragma unroll
            for (int k = 0; k < 4; k++) acc[i][j][k] = 0.0f;

    const int a_co = tid >> 2;            // 0..127
    const int a_kq = (tid & 3) * 8;
    const int b_k  = tid >> 3;            // 0..63 (row)
    const int b_t  = tid & 7;             // thread within row

    auto issue = [&](int chunk, int st) {
        const int k0 = chunk * KC;
        const uint32_t arow_off = (a_co * A_STRIDE + a_kq) * 2;
        cp16(smem_u32(smem + OFF_A(st) + arow_off),      &g_Wh[a_co * KD + k0 + a_kq]);
        cp16(smem_u32(smem + OFF_A(st) + arow_off + 64), &g_Wh[a_co * KD + k0 + a_kq + 32]);
        const int k  = k0 + b_k;
        const int c  = k / 9;
        const int rs = k - c * 9;
        const int r  = rs / 3;
        const int s  = rs - r * 3;
        // coalesced interleave: per j, 8 threads of a row write consecutive 4B
        const __half* srow = g_Xs + (size_t)s * PLANE + c * CSTRIDE + r * 222 + n_base + 2 * b_t;
        const uint32_t drow = smem_u32(smem + OFF_B(st) + (b_k * B_STRIDE + 2 * b_t) * 2);
#pragma unroll
        for (int j = 0; j < 8; j++)
            cp4(drow + j * 32, srow + j * 16);
    };

    // prologue
    issue(0, 0);
    CP_COMMIT();
    CP_WAIT0();
    __syncthreads();

    const int bt_row = (lane & 7) + ((lane >> 3) & 1) * 8;
    const int bt_col = ((lane >> 4) & 1) * 8;

    for (int i = 0; i < NCHUNK; i++) {
        const int st = i & 1, nxt = (i + 1) & 1;
        if (i + 1 < NCHUNK) { issue(i + 1, nxt); CP_COMMIT(); }

        const char* pA = smem + OFF_A(st);
        const char* pB = smem + OFF_B(st);

#pragma unroll
        for (int ks = 0; ks < 4; ks++) {
            const int kb = ks * 16;
            uint32_t ah[2][4];
#pragma unroll
            for (int mt = 0; mt < 2; mt++) {
                const int row = wm * 32 + mt * 16 + (lane & 15);
                const int col = kb + ((lane >> 4) << 3);
                ldsm_x4(ah[mt], smem_u32(pA + (row * A_STRIDE + col) * 2));
            }
            uint32_t bf[2][4];
            const int krow = kb + bt_row;
#pragma unroll
            for (int pr = 0; pr < 2; pr++) {
                const int ncol = wn * 32 + pr * 16 + bt_col;
                ldsm_x4t(bf[pr], smem_u32(pB + (krow * B_STRIDE + ncol) * 2));
            }
#pragma unroll
            for (int mt = 0; mt < 2; mt++)
#pragma unroll
                for (int nt = 0; nt < 4; nt++) {
                    const int pr = nt >> 1, hf = (nt & 1) * 2;
                    mma_f16(acc[mt][nt], ah[mt], bf[pr][hf], bf[pr][hf + 1]);
                }
        }

        if (i + 1 < NCHUNK) CP_WAIT0();
        __syncthreads();
    }

    // epilogue
#pragma unroll
    for (int mt = 0; mt < 2; mt++) {
        const int row0 = wm * 32 + mt * 16 + (lane >> 2);
#pragma unroll
        for (int nt = 0; nt < 4; nt++) {
            const int n = n_base + wn * 32 + nt * 8 + 2 * (lane & 3);
            if (n < NPIX) {
                *reinterpret_cast<float2*>(out + (size_t)row0 * NPIX + n) =
                    make_float2(acc[mt][nt][0], acc[mt][nt][1]);
                *reinterpret_cast<float2*>(out + (size_t)(row0 + 8) * NPIX + n) =
                    make_float2(acc[mt][nt][2], acc[mt][nt][3]);
            }
        }
    }
}

extern "C" void kernel_launch(void* const* d_in, const int* in_sizes, int n_in,
                              void* d_out, int out_size)
{
    const float* x = (const float*)d_in[0];   // (64, 224, 224) f32
    const float* w = (const float*)d_in[1];   // (128, 64, 3, 3) f32
    float* out = (float*)d_out;               // (128, 222, 222) f32

    split_pre_kernel<<<WBLKS + XBLKS, 256>>>(w, x);

    cudaFuncSetAttribute(conv_mma_kernel, cudaFuncAttributeMaxDynamicSharedMemorySize, SMEM_TOTAL);
    const int grid = (NPIX + BN - 1) / BN;    // 386
    conv_mma_kernel<<<grid, 512, SMEM_TOTAL>>>(out);
}